// round 4
// baseline (speedup 1.0000x reference)
#include <cuda_runtime.h>
#include <math.h>

// Problem constants
#define TT   2048      // tokens = S*B
#define HD   1024      // hidden
#define FD   4096      // ffn
#define ED   4         // experts
#define KTOP 2         // top-k
#define CAP  2048      // per-expert row capacity (worst case = all tokens)

// ---- scratch (device globals: allocation-free contract) ----
__device__ int   g_cnt[ED];
__device__ int   g_rows[ED * CAP];          // gathered token index per expert row
__device__ int   g_slot_e[TT * KTOP];       // per-token slot -> expert id (-1 none)
__device__ int   g_slot_p[TT * KTOP];       // per-token slot -> gathered row pos
__device__ float g_act[(size_t)ED * CAP * FD];  // fc1 output (post-gelu), 128 MB
__device__ float g_y[(size_t)ED * CAP * HD];    // fc2 output, 32 MB

__global__ void zero_cnt_kernel() {
    if (threadIdx.x < ED) g_cnt[threadIdx.x] = 0;
}

__global__ void router_kernel(const float* __restrict__ probs) {
    int t = blockIdx.x * blockDim.x + threadIdx.x;
    if (t >= TT) return;
    int slot = 0;
#pragma unroll
    for (int e = 0; e < ED; e++) {
        float p = probs[t * ED + e];
        if (p > 0.0f && slot < KTOP) {
            int pos = atomicAdd(&g_cnt[e], 1);
            g_rows[e * CAP + pos]    = t;
            g_slot_e[t * KTOP + slot] = e;
            g_slot_p[t * KTOP + slot] = pos;
            slot++;
        }
    }
    for (; slot < KTOP; slot++) g_slot_e[t * KTOP + slot] = -1;
}

__device__ __forceinline__ float gelu_exact(float x) {
    return 0.5f * x * (1.0f + erff(x * 0.70710678118654752440f));
}

// ============================================================================
// fc1: C[r, n] = gelu( sum_k X[rows[e][r], k] * W1[e, k, n] )  -> g_act
// BM=BN=128, BK=16, 256 threads, 8x8 per-thread micro-tile.
// ============================================================================
__global__ __launch_bounds__(256, 2)
void fc1_kernel(const float* __restrict__ X, const float* __restrict__ W1) {
    const int e = blockIdx.z;
    const int cnt = g_cnt[e];
    const int row0 = blockIdx.y * 128;
    if (row0 >= cnt) return;
    const int col0 = blockIdx.x * 128;

    __shared__ __align__(16) float As[16][128];
    __shared__ __align__(16) float Bs[16][128];

    const int tid = threadIdx.x;
    const int tx = tid % 16;   // 8-col group
    const int ty = tid / 16;   // 8-row group

    // A-load mapping: each thread loads one row's 8 contiguous k's (2 x float4)
    const int arow = tid >> 1;            // 0..127
    const int ak   = (tid & 1) * 8;       // 0 or 8
    const int grow = row0 + arow;
    const int tok  = g_rows[e * CAP + (grow < cnt ? grow : 0)];
    const float* __restrict__ Xrow = X + (size_t)tok * HD;
    const float* __restrict__ Wb   = W1 + (size_t)e * HD * FD;

    float acc[8][8];
#pragma unroll
    for (int i = 0; i < 8; i++)
#pragma unroll
        for (int j = 0; j < 8; j++) acc[i][j] = 0.0f;

    for (int k0 = 0; k0 < HD; k0 += 16) {
        // load A tile (gathered rows)
        float4 a0 = *(const float4*)(Xrow + k0 + ak);
        float4 a1 = *(const float4*)(Xrow + k0 + ak + 4);
        As[ak + 0][arow] = a0.x; As[ak + 1][arow] = a0.y;
        As[ak + 2][arow] = a0.z; As[ak + 3][arow] = a0.w;
        As[ak + 4][arow] = a1.x; As[ak + 5][arow] = a1.y;
        As[ak + 6][arow] = a1.z; As[ak + 7][arow] = a1.w;
        // load B tile: 512 float4 across 256 threads (2 each), coalesced in n
        {
            int j = tid;
            int bk = j >> 5, bn = (j & 31) * 4;
            *(float4*)&Bs[bk][bn] = *(const float4*)(Wb + (size_t)(k0 + bk) * FD + col0 + bn);
            j = tid + 256;
            bk = j >> 5; bn = (j & 31) * 4;
            *(float4*)&Bs[bk][bn] = *(const float4*)(Wb + (size_t)(k0 + bk) * FD + col0 + bn);
        }
        __syncthreads();
#pragma unroll
        for (int k = 0; k < 16; k++) {
            float4 av0 = *(const float4*)&As[k][ty * 8];
            float4 av1 = *(const float4*)&As[k][ty * 8 + 4];
            float4 bv0 = *(const float4*)&Bs[k][tx * 8];
            float4 bv1 = *(const float4*)&Bs[k][tx * 8 + 4];
            float ar[8] = {av0.x, av0.y, av0.z, av0.w, av1.x, av1.y, av1.z, av1.w};
            float br[8] = {bv0.x, bv0.y, bv0.z, bv0.w, bv1.x, bv1.y, bv1.z, bv1.w};
#pragma unroll
            for (int i = 0; i < 8; i++)
#pragma unroll
                for (int j = 0; j < 8; j++) acc[i][j] += ar[i] * br[j];
        }
        __syncthreads();
    }

    // epilogue: gelu + store
#pragma unroll
    for (int i = 0; i < 8; i++) {
        int r = row0 + ty * 8 + i;
        if (r >= cnt) continue;
        float* dst = g_act + ((size_t)e * CAP + r) * FD + col0 + tx * 8;
        float4 v0, v1;
        v0.x = gelu_exact(acc[i][0]); v0.y = gelu_exact(acc[i][1]);
        v0.z = gelu_exact(acc[i][2]); v0.w = gelu_exact(acc[i][3]);
        v1.x = gelu_exact(acc[i][4]); v1.y = gelu_exact(acc[i][5]);
        v1.z = gelu_exact(acc[i][6]); v1.w = gelu_exact(acc[i][7]);
        *(float4*)dst = v0;
        *(float4*)(dst + 4) = v1;
    }
}

// ============================================================================
// fc2: Y[r, n] = sum_k g_act[e, r, k] * W2[e, k, n]   (K = FD, N = HD)
// ============================================================================
__global__ __launch_bounds__(256, 2)
void fc2_kernel(const float* __restrict__ W2) {
    const int e = blockIdx.z;
    const int cnt = g_cnt[e];
    const int row0 = blockIdx.y * 128;
    if (row0 >= cnt) return;
    const int col0 = blockIdx.x * 128;

    __shared__ __align__(16) float As[16][128];
    __shared__ __align__(16) float Bs[16][128];

    const int tid = threadIdx.x;
    const int tx = tid % 16;
    const int ty = tid / 16;

    const int arow = tid >> 1;
    const int ak   = (tid & 1) * 8;
    const float* __restrict__ Arow = g_act + ((size_t)e * CAP + row0 + arow) * FD;
    const float* __restrict__ Wb   = W2 + (size_t)e * FD * HD;

    float acc[8][8];
#pragma unroll
    for (int i = 0; i < 8; i++)
#pragma unroll
        for (int j = 0; j < 8; j++) acc[i][j] = 0.0f;

    for (int k0 = 0; k0 < FD; k0 += 16) {
        float4 a0 = *(const float4*)(Arow + k0 + ak);
        float4 a1 = *(const float4*)(Arow + k0 + ak + 4);
        As[ak + 0][arow] = a0.x; As[ak + 1][arow] = a0.y;
        As[ak + 2][arow] = a0.z; As[ak + 3][arow] = a0.w;
        As[ak + 4][arow] = a1.x; As[ak + 5][arow] = a1.y;
        As[ak + 6][arow] = a1.z; As[ak + 7][arow] = a1.w;
        {
            int j = tid;
            int bk = j >> 5, bn = (j & 31) * 4;
            *(float4*)&Bs[bk][bn] = *(const float4*)(Wb + (size_t)(k0 + bk) * HD + col0 + bn);
            j = tid + 256;
            bk = j >> 5; bn = (j & 31) * 4;
            *(float4*)&Bs[bk][bn] = *(const float4*)(Wb + (size_t)(k0 + bk) * HD + col0 + bn);
        }
        __syncthreads();
#pragma unroll
        for (int k = 0; k < 16; k++) {
            float4 av0 = *(const float4*)&As[k][ty * 8];
            float4 av1 = *(const float4*)&As[k][ty * 8 + 4];
            float4 bv0 = *(const float4*)&Bs[k][tx * 8];
            float4 bv1 = *(const float4*)&Bs[k][tx * 8 + 4];
            float ar[8] = {av0.x, av0.y, av0.z, av0.w, av1.x, av1.y, av1.z, av1.w};
            float br[8] = {bv0.x, bv0.y, bv0.z, bv0.w, bv1.x, bv1.y, bv1.z, bv1.w};
#pragma unroll
            for (int i = 0; i < 8; i++)
#pragma unroll
                for (int j = 0; j < 8; j++) acc[i][j] += ar[i] * br[j];
        }
        __syncthreads();
    }

#pragma unroll
    for (int i = 0; i < 8; i++) {
        int r = row0 + ty * 8 + i;
        if (r >= cnt) continue;
        float* dst = g_y + ((size_t)e * CAP + r) * HD + col0 + tx * 8;
        float4 v0 = {acc[i][0], acc[i][1], acc[i][2], acc[i][3]};
        float4 v1 = {acc[i][4], acc[i][5], acc[i][6], acc[i][7]};
        *(float4*)dst = v0;
        *(float4*)(dst + 4) = v1;
    }
}

// ============================================================================
// combine: out[t,h] = residual[t,h] + sum_slot gate * Y[slot_row, h]
// Deterministic (fixed slot order), no atomics.
// ============================================================================
__global__ void combine_kernel(const float* __restrict__ residual,
                               const float* __restrict__ probs,
                               float* __restrict__ out) {
    int i = blockIdx.x * blockDim.x + threadIdx.x;   // over TT*HD/4
    if (i >= TT * HD / 4) return;
    int t  = i / (HD / 4);
    int h4 = i % (HD / 4);
    float4 acc = ((const float4*)residual)[i];
#pragma unroll
    for (int s = 0; s < KTOP; s++) {
        int e = g_slot_e[t * KTOP + s];
        if (e < 0) continue;
        int pos = g_slot_p[t * KTOP + s];
        float g = probs[t * ED + e];
        const float4 y = *(const float4*)(g_y + ((size_t)e * CAP + pos) * HD + h4 * 4);
        acc.x += g * y.x; acc.y += g * y.y; acc.z += g * y.z; acc.w += g * y.w;
    }
    ((float4*)out)[i] = acc;
}

extern "C" void kernel_launch(void* const* d_in, const int* in_sizes, int n_in,
                              void* d_out, int out_size) {
    const float* hidden   = (const float*)d_in[0];   // [S,B,H] == [T,H]
    const float* residual = (const float*)d_in[1];   // [T,H]
    const float* probs    = (const float*)d_in[2];   // [T,E]
    // d_in[3] routing_map: redundant (probs==0 where unrouted)
    const float* w1       = (const float*)d_in[4];   // [E,H,F]
    const float* w2       = (const float*)d_in[5];   // [E,F,H]
    float* out            = (float*)d_out;

    zero_cnt_kernel<<<1, 32>>>();
    router_kernel<<<TT / 256, 256>>>(probs);
    fc1_kernel<<<dim3(FD / 128, CAP / 128, ED), 256>>>(hidden, w1);
    fc2_kernel<<<dim3(HD / 128, CAP / 128, ED), 256>>>(w2);
    combine_kernel<<<(TT * HD / 4 + 255) / 256, 256>>>(residual, probs, out);
}

// round 8
// speedup vs baseline: 1.6932x; 1.6932x over previous
#include <cuda_runtime.h>
#include <cuda_bf16.h>
#include <math.h>

// ---------------- problem constants ----------------
#define TT   2048
#define HD   1024
#define FD   4096
#define ED   4
#define KTOP 2
#define CAP  2048

// GEMM tiling
#define BM   256
#define BN   128
#define BKH  64            // k-chunk in bf16 elements (128 bytes per row)
#define NTHR 512

// ---------------- scratch (device globals) ----------------
__device__ int g_cnt[ED];
__device__ int g_rows[ED * CAP];
__device__ int g_slot_e[TT * KTOP];
__device__ int g_slot_p[TT * KTOP];

// split-bf16, K-extended operands
__device__ __align__(16) __nv_bfloat16 g_xs  [(size_t)TT * 3 * HD];        // [T, 3H]  (hi|hi|lo)
__device__ __align__(16) __nv_bfloat16 g_w1t [(size_t)ED * FD * 3 * HD];   // [E,F,3H] (hi|lo|hi)
__device__ __align__(16) __nv_bfloat16 g_w2t [(size_t)ED * HD * 3 * FD];   // [E,H,3F] (hi|lo|hi)
__device__ __align__(16) __nv_bfloat16 g_act3[(size_t)ED * CAP * 3 * FD];  // [E,CAP,3F] (hi|hi|lo)
__device__ __align__(16) float         g_y   [(size_t)ED * CAP * HD];

// ---------------- helpers ----------------
__device__ __forceinline__ unsigned smem_u32_of(const void* p) {
    unsigned a;
    asm("{ .reg .u64 t; cvta.to.shared.u64 t, %1; cvt.u32.u64 %0, t; }" : "=r"(a) : "l"(p));
    return a;
}
__device__ __forceinline__ void cp16(unsigned dst, const void* src) {
    asm volatile("cp.async.cg.shared.global [%0], [%1], 16;" :: "r"(dst), "l"(src));
}
__device__ __forceinline__ unsigned pack_bf16(float a, float b) {
    unsigned r;
    asm("cvt.rn.bf16x2.f32 %0, %1, %2;" : "=r"(r) : "f"(b), "f"(a));  // lo=a, hi=b
    return r;
}
__device__ __forceinline__ float gelu_exact(float x) {
    return 0.5f * x * (1.0f + erff(x * 0.70710678118654752440f));
}

#define LDSM4(R, addr) \
    asm volatile("ldmatrix.sync.aligned.m8n8.x4.shared.b16 {%0,%1,%2,%3}, [%4];" \
        : "=r"((R)[0]), "=r"((R)[1]), "=r"((R)[2]), "=r"((R)[3]) : "r"(addr))

__device__ __forceinline__ void mma_bf16(float* c, const unsigned* a, const unsigned* b) {
    asm volatile(
        "mma.sync.aligned.m16n8k16.row.col.f32.bf16.bf16.f32 "
        "{%0,%1,%2,%3}, {%4,%5,%6,%7}, {%8,%9}, {%0,%1,%2,%3};"
        : "+f"(c[0]), "+f"(c[1]), "+f"(c[2]), "+f"(c[3])
        : "r"(a[0]), "r"(a[1]), "r"(a[2]), "r"(a[3]), "r"(b[0]), "r"(b[1]));
}

// ---------------- routing ----------------
__global__ void zero_cnt_kernel() {
    if (threadIdx.x < ED) g_cnt[threadIdx.x] = 0;
}

__global__ void router_kernel(const float* __restrict__ probs) {
    int t = blockIdx.x * blockDim.x + threadIdx.x;
    if (t >= TT) return;
    int slot = 0;
#pragma unroll
    for (int e = 0; e < ED; e++) {
        float p = probs[t * ED + e];
        if (p > 0.0f && slot < KTOP) {
            int pos = atomicAdd(&g_cnt[e], 1);
            g_rows[e * CAP + pos] = t;
            g_slot_e[t * KTOP + slot] = e;
            g_slot_p[t * KTOP + slot] = pos;
            slot++;
        }
    }
    for (; slot < KTOP; slot++) g_slot_e[t * KTOP + slot] = -1;
}

// ---------------- split-bf16 prepass ----------------
__global__ void split_x_kernel(const float* __restrict__ x) {
    int i = blockIdx.x * blockDim.x + threadIdx.x;  // over TT*HD
    if (i >= TT * HD) return;
    int t = i / HD, h = i % HD;
    float v = x[i];
    __nv_bfloat16 hi = __float2bfloat16(v);
    __nv_bfloat16 lo = __float2bfloat16(v - __bfloat162float(hi));
    size_t b = (size_t)t * (3 * HD);
    g_xs[b + h]          = hi;
    g_xs[b + HD + h]     = hi;
    g_xs[b + 2 * HD + h] = lo;
}

// w1[e][h][f] -> g_w1t[e][f][3H]  segments (hi | lo | hi)
__global__ void split_w1_kernel(const float* __restrict__ w1) {
    __shared__ float tile[32][33];
    int e = blockIdx.z, f0 = blockIdx.x * 32, h0 = blockIdx.y * 32;
    int tx = threadIdx.x, ty = threadIdx.y;
    const float* src = w1 + (size_t)e * HD * FD;
    for (int j = ty; j < 32; j += 8)
        tile[j][tx] = src[(size_t)(h0 + j) * FD + f0 + tx];
    __syncthreads();
    for (int j = ty; j < 32; j += 8) {
        float v = tile[tx][j];  // w1[h0+tx][f0+j]
        __nv_bfloat16 hi = __float2bfloat16(v);
        __nv_bfloat16 lo = __float2bfloat16(v - __bfloat162float(hi));
        size_t b = ((size_t)e * FD + f0 + j) * (size_t)(3 * HD);
        g_w1t[b + h0 + tx]          = hi;
        g_w1t[b + HD + h0 + tx]     = lo;
        g_w1t[b + 2 * HD + h0 + tx] = hi;
    }
}

// w2[e][f][h] -> g_w2t[e][h][3F]  segments (hi | lo | hi)
__global__ void split_w2_kernel(const float* __restrict__ w2) {
    __shared__ float tile[32][33];
    int e = blockIdx.z, h0 = blockIdx.x * 32, f0 = blockIdx.y * 32;
    int tx = threadIdx.x, ty = threadIdx.y;
    const float* src = w2 + (size_t)e * FD * HD;
    for (int j = ty; j < 32; j += 8)
        tile[j][tx] = src[(size_t)(f0 + j) * HD + h0 + tx];
    __syncthreads();
    for (int j = ty; j < 32; j += 8) {
        float v = tile[tx][j];  // w2[f0+tx][h0+j]
        __nv_bfloat16 hi = __float2bfloat16(v);
        __nv_bfloat16 lo = __float2bfloat16(v - __bfloat162float(hi));
        size_t b = ((size_t)e * HD + h0 + j) * (size_t)(3 * FD);
        g_w2t[b + f0 + tx]          = hi;
        g_w2t[b + FD + f0 + tx]     = lo;
        g_w2t[b + 2 * FD + f0 + tx] = hi;
    }
}

// ---------------- mma.sync GEMM (split-bf16 K-extended) ----------------
// MODE 0: fc1  A = g_xs (gathered rows),  B = g_w1t, K'=3H, epi: gelu->split->g_act3
// MODE 1: fc2  A = g_act3 (direct rows),  B = g_w2t, K'=3F, epi: fp32 -> g_y
//
// smem per buffer: A 256x128B = 32KB, B 128x128B = 16KB, double buffered.
// Layout: row-major 128B rows, 16B chunk index XOR-swizzled with (row & 7).

#define OFF_A0 0
#define OFF_A1 32768
#define OFF_B0 65536
#define OFF_B1 (65536 + 16384)
#define SMEM_BYTES (98304 + 1024)

__device__ __forceinline__ unsigned sw_off(int row, int c16) {
    return (unsigned)(row * 128 + ((c16 ^ (row & 7)) * 16));
}

template <int KP, int MODE>
__global__ void __launch_bounds__(NTHR, 1)
gemm_mma_kernel() {
    const int e = blockIdx.z;
    const int cnt = g_cnt[e];
    const int row0 = blockIdx.y * BM;
    if (row0 >= cnt) return;
    const int col0 = blockIdx.x * BN;

    extern __shared__ char smem_raw[];
    const unsigned sb0 = smem_u32_of(smem_raw);
    const unsigned sb = (sb0 + 1023u) & ~1023u;

    const int tid = threadIdx.x;
    const int wid = tid >> 5;
    const int lane = tid & 31;
    const int wm = wid >> 2;          // 0..3  (m block of 64)
    const int wn = wid & 3;           // 0..3  (n block of 32)

    // ---- per-thread load mapping ----
    // A: row = tid>>1 (0..255), chunks (tid&1)*4 .. +3
    // B: row = tid>>2 (0..127), chunks (tid&3)*2 .. +1
    const int a_row = tid >> 1;
    const int a_c0  = (tid & 1) * 4;
    const int b_row = tid >> 2;
    const int b_c0  = (tid & 3) * 2;

    const __nv_bfloat16* a_src;
    if (MODE == 0) {
        int r = row0 + a_row; if (r >= cnt) r = cnt - 1;
        a_src = g_xs + (size_t)g_rows[e * CAP + r] * KP;
    } else {
        int r = row0 + a_row; if (r >= cnt) r = cnt - 1;
        a_src = g_act3 + ((size_t)e * CAP + r) * KP;
    }
    const int NB = (MODE == 0) ? FD : HD;
    const __nv_bfloat16* Bbase = (MODE == 0) ? g_w1t : g_w2t;
    const __nv_bfloat16* b_src = Bbase + ((size_t)e * NB + col0 + b_row) * KP;

    float acc[4][4][4];
#pragma unroll
    for (int i = 0; i < 4; i++)
#pragma unroll
        for (int j = 0; j < 4; j++)
#pragma unroll
            for (int q = 0; q < 4; q++) acc[i][j][q] = 0.0f;

    const int NCH = KP / BKH;

    // ---- chunk loader ----
    auto load_chunk = [&](int c, int buf) {
        const unsigned offA = buf ? OFF_A1 : OFF_A0;
        const unsigned offB = buf ? OFF_B1 : OFF_B0;
        const __nv_bfloat16* ap = a_src + c * BKH + a_c0 * 8;
#pragma unroll
        for (int i = 0; i < 4; i++)
            cp16(sb + offA + sw_off(a_row, a_c0 + i), ap + i * 8);
        const __nv_bfloat16* bp = b_src + c * BKH + b_c0 * 8;
#pragma unroll
        for (int i = 0; i < 2; i++)
            cp16(sb + offB + sw_off(b_row, b_c0 + i), bp + i * 8);
    };

    load_chunk(0, 0);
    asm volatile("cp.async.commit_group;" ::: "memory");

    for (int c = 0; c < NCH; ++c) {
        const int buf = c & 1;
        if (c + 1 < NCH) {
            load_chunk(c + 1, (c + 1) & 1);
            asm volatile("cp.async.commit_group;" ::: "memory");
            asm volatile("cp.async.wait_group 1;" ::: "memory");
        } else {
            asm volatile("cp.async.wait_group 0;" ::: "memory");
        }
        __syncthreads();

        const unsigned abuf = sb + (buf ? OFF_A1 : OFF_A0);
        const unsigned bbuf = sb + (buf ? OFF_B1 : OFF_B0);
#pragma unroll
        for (int kk = 0; kk < 4; kk++) {
            unsigned afr[4][4];
#pragma unroll
            for (int mi = 0; mi < 4; mi++) {
                int row = wm * 64 + mi * 16 + (lane & 15);
                int c16 = kk * 2 + (lane >> 4);
                LDSM4(afr[mi], abuf + sw_off(row, c16));
            }
            unsigned bfr[4][2];
#pragma unroll
            for (int nj = 0; nj < 2; nj++) {
                int row = wn * 32 + nj * 16 + ((lane >> 4) * 8) + (lane & 7);
                int c16 = kk * 2 + ((lane >> 3) & 1);
                unsigned r4[4];
                LDSM4(r4, bbuf + sw_off(row, c16));
                bfr[nj * 2][0] = r4[0]; bfr[nj * 2][1] = r4[1];
                bfr[nj * 2 + 1][0] = r4[2]; bfr[nj * 2 + 1][1] = r4[3];
            }
#pragma unroll
            for (int mi = 0; mi < 4; mi++)
#pragma unroll
                for (int ni = 0; ni < 4; ni++)
                    mma_bf16(acc[mi][ni], afr[mi], bfr[ni]);
        }
        __syncthreads();
    }

    // ---- epilogue ----
    const int rq = lane >> 2;          // 0..7 row within 8
    const int cp = lane & 3;           // col pair

#pragma unroll
    for (int mi = 0; mi < 4; mi++) {
#pragma unroll
        for (int ni = 0; ni < 4; ni++) {
            int col = col0 + wn * 32 + ni * 8 + 2 * cp;
#pragma unroll
            for (int half = 0; half < 2; half++) {
                int r = row0 + wm * 64 + mi * 16 + rq + half * 8;
                if (r >= cnt) continue;
                float v0 = acc[mi][ni][half * 2];
                float v1 = acc[mi][ni][half * 2 + 1];
                if (MODE == 0) {
                    v0 = gelu_exact(v0);
                    v1 = gelu_exact(v1);
                    float h0 = __bfloat162float(__float2bfloat16(v0));
                    float h1 = __bfloat162float(__float2bfloat16(v1));
                    unsigned hp = pack_bf16(h0, h1);
                    unsigned lp = pack_bf16(v0 - h0, v1 - h1);
                    __nv_bfloat16* dst = g_act3 + ((size_t)e * CAP + r) * (size_t)(3 * FD) + col;
                    *(unsigned*)(dst)          = hp;
                    *(unsigned*)(dst + FD)     = hp;
                    *(unsigned*)(dst + 2 * FD) = lp;
                } else {
                    float* dst = g_y + ((size_t)e * CAP + r) * HD + col;
                    *(float2*)dst = make_float2(v0, v1);
                }
            }
        }
    }
}

// ---------------- combine ----------------
__global__ void combine_kernel(const float* __restrict__ residual,
                               const float* __restrict__ probs,
                               float* __restrict__ out) {
    int i = blockIdx.x * blockDim.x + threadIdx.x;
    if (i >= TT * HD / 4) return;
    int t = i / (HD / 4);
    int h4 = i % (HD / 4);
    float4 acc = ((const float4*)residual)[i];
#pragma unroll
    for (int s = 0; s < KTOP; s++) {
        int e = g_slot_e[t * KTOP + s];
        if (e < 0) continue;
        int pos = g_slot_p[t * KTOP + s];
        float g = probs[t * ED + e];
        const float4 y = *(const float4*)(g_y + ((size_t)e * CAP + pos) * HD + h4 * 4);
        acc.x += g * y.x; acc.y += g * y.y; acc.z += g * y.z; acc.w += g * y.w;
    }
    ((float4*)out)[i] = acc;
}

// ---------------- launch ----------------
extern "C" void kernel_launch(void* const* d_in, const int* in_sizes, int n_in,
                              void* d_out, int out_size) {
    const float* hidden   = (const float*)d_in[0];
    const float* residual = (const float*)d_in[1];
    const float* probs    = (const float*)d_in[2];
    const float* w1       = (const float*)d_in[4];
    const float* w2       = (const float*)d_in[5];
    float* out            = (float*)d_out;

    cudaFuncSetAttribute(gemm_mma_kernel<3 * HD, 0>,
                         cudaFuncAttributeMaxDynamicSharedMemorySize, SMEM_BYTES);
    cudaFuncSetAttribute(gemm_mma_kernel<3 * FD, 1>,
                         cudaFuncAttributeMaxDynamicSharedMemorySize, SMEM_BYTES);

    zero_cnt_kernel<<<1, 32>>>();
    router_kernel<<<TT / 256, 256>>>(probs);
    split_x_kernel<<<(TT * HD) / 256, 256>>>(hidden);
    split_w1_kernel<<<dim3(FD / 32, HD / 32, ED), dim3(32, 8)>>>(w1);
    split_w2_kernel<<<dim3(HD / 32, FD / 32, ED), dim3(32, 8)>>>(w2);

    gemm_mma_kernel<3 * HD, 0><<<dim3(FD / BN, CAP / BM, ED), NTHR, SMEM_BYTES>>>();
    gemm_mma_kernel<3 * FD, 1><<<dim3(HD / BN, CAP / BM, ED), NTHR, SMEM_BYTES>>>();

    combine_kernel<<<(TT * HD / 4 + 255) / 256, 256>>>(residual, probs, out);
}

// round 17
// speedup vs baseline: 1.8975x; 1.1207x over previous
#include <cuda_runtime.h>
#include <cuda_bf16.h>
#include <math.h>

// ---------------- problem constants ----------------
#define TT   2048
#define HD   1024
#define FD   4096
#define ED   4
#define KTOP 2
#define CAP  2048

// GEMM tiling
#define BM   256
#define BN   128
#define BKH  64            // k-chunk in bf16 elements (128 bytes per row)
#define NTHR 512
#define NSTG 3

// ---------------- scratch (device globals) ----------------
__device__ int g_cnt[ED];
__device__ int g_rows[ED * CAP];
__device__ int g_slot_e[TT * KTOP];
__device__ int g_slot_p[TT * KTOP];

// split-bf16, K-extended operands (round-8 proven layouts)
__device__ __align__(16) __nv_bfloat16 g_xs  [(size_t)TT * 3 * HD];        // [T, 3H]  (hi|hi|lo)
__device__ __align__(16) __nv_bfloat16 g_w1t [(size_t)ED * FD * 3 * HD];   // [E,F,3H] (hi|lo|hi)
__device__ __align__(16) __nv_bfloat16 g_w2t [(size_t)ED * HD * 3 * FD];   // [E,H,3F] (hi|lo|hi)
__device__ __align__(16) __nv_bfloat16 g_act3[(size_t)ED * CAP * 3 * FD];  // [E,CAP,3F] (hi|hi|lo)
__device__ __align__(16) float         g_y   [(size_t)ED * CAP * HD];

// ---------------- helpers ----------------
__device__ __forceinline__ unsigned smem_u32_of(const void* p) {
    unsigned a;
    asm("{ .reg .u64 t; cvta.to.shared.u64 t, %1; cvt.u32.u64 %0, t; }" : "=r"(a) : "l"(p));
    return a;
}
__device__ __forceinline__ void cp16(unsigned dst, const void* src) {
    asm volatile("cp.async.cg.shared.global [%0], [%1], 16;" :: "r"(dst), "l"(src));
}
__device__ __forceinline__ unsigned pack_bf16(float a, float b) {
    unsigned r;
    asm("cvt.rn.bf16x2.f32 %0, %1, %2;" : "=r"(r) : "f"(b), "f"(a));  // lo=a, hi=b
    return r;
}
__device__ __forceinline__ float gelu_exact(float x) {
    return 0.5f * x * (1.0f + erff(x * 0.70710678118654752440f));
}

#define LDSM4(R, addr) \
    asm volatile("ldmatrix.sync.aligned.m8n8.x4.shared.b16 {%0,%1,%2,%3}, [%4];" \
        : "=r"((R)[0]), "=r"((R)[1]), "=r"((R)[2]), "=r"((R)[3]) : "r"(addr))

__device__ __forceinline__ void mma_bf16(float* c, const unsigned* a, const unsigned* b) {
    asm volatile(
        "mma.sync.aligned.m16n8k16.row.col.f32.bf16.bf16.f32 "
        "{%0,%1,%2,%3}, {%4,%5,%6,%7}, {%8,%9}, {%0,%1,%2,%3};"
        : "+f"(c[0]), "+f"(c[1]), "+f"(c[2]), "+f"(c[3])
        : "r"(a[0]), "r"(a[1]), "r"(a[2]), "r"(a[3]), "r"(b[0]), "r"(b[1]));
}

// ---------------- routing ----------------
__global__ void zero_cnt_kernel() {
    if (threadIdx.x < ED) g_cnt[threadIdx.x] = 0;
}

__global__ void router_kernel(const float* __restrict__ probs) {
    int t = blockIdx.x * blockDim.x + threadIdx.x;
    if (t >= TT) return;
    int slot = 0;
#pragma unroll
    for (int e = 0; e < ED; e++) {
        float p = probs[t * ED + e];
        if (p > 0.0f && slot < KTOP) {
            int pos = atomicAdd(&g_cnt[e], 1);
            g_rows[e * CAP + pos] = t;
            g_slot_e[t * KTOP + slot] = e;
            g_slot_p[t * KTOP + slot] = pos;
            slot++;
        }
    }
    for (; slot < KTOP; slot++) g_slot_e[t * KTOP + slot] = -1;
}

// ---------------- split-bf16 prepass (round-8 proven) ----------------
__global__ void split_x_kernel(const float* __restrict__ x) {
    int i = blockIdx.x * blockDim.x + threadIdx.x;  // over TT*HD
    if (i >= TT * HD) return;
    int t = i / HD, h = i % HD;
    float v = x[i];
    __nv_bfloat16 hi = __float2bfloat16(v);
    __nv_bfloat16 lo = __float2bfloat16(v - __bfloat162float(hi));
    size_t b = (size_t)t * (3 * HD);
    g_xs[b + h]          = hi;
    g_xs[b + HD + h]     = hi;
    g_xs[b + 2 * HD + h] = lo;
}

// w1[e][h][f] -> g_w1t[e][f][3H]  segments (hi | lo | hi)
__global__ void split_w1_kernel(const float* __restrict__ w1) {
    __shared__ float tile[32][33];
    int e = blockIdx.z, f0 = blockIdx.x * 32, h0 = blockIdx.y * 32;
    int tx = threadIdx.x, ty = threadIdx.y;
    const float* src = w1 + (size_t)e * HD * FD;
    for (int j = ty; j < 32; j += 8)
        tile[j][tx] = src[(size_t)(h0 + j) * FD + f0 + tx];
    __syncthreads();
    for (int j = ty; j < 32; j += 8) {
        float v = tile[tx][j];  // w1[h0+tx][f0+j]
        __nv_bfloat16 hi = __float2bfloat16(v);
        __nv_bfloat16 lo = __float2bfloat16(v - __bfloat162float(hi));
        size_t b = ((size_t)e * FD + f0 + j) * (size_t)(3 * HD);
        g_w1t[b + h0 + tx]          = hi;
        g_w1t[b + HD + h0 + tx]     = lo;
        g_w1t[b + 2 * HD + h0 + tx] = hi;
    }
}

// w2[e][f][h] -> g_w2t[e][h][3F]  segments (hi | lo | hi)
__global__ void split_w2_kernel(const float* __restrict__ w2) {
    __shared__ float tile[32][33];
    int e = blockIdx.z, h0 = blockIdx.x * 32, f0 = blockIdx.y * 32;
    int tx = threadIdx.x, ty = threadIdx.y;
    const float* src = w2 + (size_t)e * FD * HD;
    for (int j = ty; j < 32; j += 8)
        tile[j][tx] = src[(size_t)(f0 + j) * HD + h0 + tx];
    __syncthreads();
    for (int j = ty; j < 32; j += 8) {
        float v = tile[tx][j];  // w2[f0+tx][h0+j]
        __nv_bfloat16 hi = __float2bfloat16(v);
        __nv_bfloat16 lo = __float2bfloat16(v - __bfloat162float(hi));
        size_t b = ((size_t)e * HD + h0 + j) * (size_t)(3 * FD);
        g_w2t[b + f0 + tx]          = hi;
        g_w2t[b + FD + f0 + tx]     = lo;
        g_w2t[b + 2 * FD + f0 + tx] = hi;
    }
}

// ---------------- mma.sync GEMM (bf16 3-term, 3-stage pipeline) ----------------
// MODE 0: fc1  A = g_xs (gathered rows),  B = g_w1t, K'=3H, epi: gelu->split->g_act3
// MODE 1: fc2  A = g_act3 (direct rows),  B = g_w2t, K'=3F, epi: fp32 -> g_y
//
// smem per stage: A 256x128B = 32KB, B 128x128B = 16KB -> 48KB; 3 stages.
// Hazard chain verified: compute(c-1) -> __syncthreads at iter c -> load(c+2)
// targets stage (c-1)%3; one barrier per chunk suffices.

#define STG_BYTES 49152
#define SMEM_BYTES (NSTG * STG_BYTES + 1024)

__device__ __forceinline__ unsigned sw_off(int row, int c16) {
    return (unsigned)(row * 128 + ((c16 ^ (row & 7)) * 16));
}

template <int KP, int MODE>
__global__ void __launch_bounds__(NTHR, 1)
gemm_mma_kernel() {
    const int e = blockIdx.z;
    const int cnt = g_cnt[e];
    const int row0 = blockIdx.y * BM;
    if (row0 >= cnt) return;
    const int col0 = blockIdx.x * BN;

    extern __shared__ char smem_raw[];
    const unsigned sb0 = smem_u32_of(smem_raw);
    const unsigned sb = (sb0 + 1023u) & ~1023u;

    const int tid = threadIdx.x;
    const int wid = tid >> 5;
    const int lane = tid & 31;
    const int wm = wid >> 2;          // 0..3 (m block of 64)
    const int wn = wid & 3;           // 0..3 (n block of 32)

    // ---- per-thread load mapping (round-8 proven) ----
    const int a_row = tid >> 1;           // 0..255
    const int a_c0  = (tid & 1) * 4;      // 16B chunk base
    const int b_row = tid >> 2;           // 0..127
    const int b_c0  = (tid & 3) * 2;

    const __nv_bfloat16* a_src;
    {
        int r = row0 + a_row; if (r >= cnt) r = cnt - 1;
        if (MODE == 0) a_src = g_xs + (size_t)g_rows[e * CAP + r] * KP;
        else           a_src = g_act3 + ((size_t)e * CAP + r) * KP;
    }
    const int NB = (MODE == 0) ? FD : HD;
    const __nv_bfloat16* Bbase = (MODE == 0) ? g_w1t : g_w2t;
    const __nv_bfloat16* b_src = Bbase + ((size_t)e * NB + col0 + b_row) * KP;

    float acc[4][4][4];
#pragma unroll
    for (int i = 0; i < 4; i++)
#pragma unroll
        for (int j = 0; j < 4; j++)
#pragma unroll
            for (int q = 0; q < 4; q++) acc[i][j][q] = 0.0f;

    const int NCH = KP / BKH;

    auto load_chunk = [&](int c) {
        const int stg = c % NSTG;
        const unsigned offA = (unsigned)(stg * STG_BYTES);
        const unsigned offB = offA + 32768u;
        const __nv_bfloat16* ap = a_src + c * BKH + a_c0 * 8;
#pragma unroll
        for (int i = 0; i < 4; i++)
            cp16(sb + offA + sw_off(a_row, a_c0 + i), ap + i * 8);
        const __nv_bfloat16* bp = b_src + c * BKH + b_c0 * 8;
#pragma unroll
        for (int i = 0; i < 2; i++)
            cp16(sb + offB + sw_off(b_row, b_c0 + i), bp + i * 8);
    };

    load_chunk(0);
    asm volatile("cp.async.commit_group;" ::: "memory");
    load_chunk(1);
    asm volatile("cp.async.commit_group;" ::: "memory");

    for (int c = 0; c < NCH; ++c) {
        if (c + 1 < NCH) asm volatile("cp.async.wait_group 1;" ::: "memory");
        else             asm volatile("cp.async.wait_group 0;" ::: "memory");
        __syncthreads();

        const int stg = c % NSTG;
        const unsigned abuf = sb + (unsigned)(stg * STG_BYTES);
        const unsigned bbuf = abuf + 32768u;
#pragma unroll
        for (int kk = 0; kk < 4; kk++) {
            unsigned afr[4][4];
#pragma unroll
            for (int mi = 0; mi < 4; mi++) {
                int row = wm * 64 + mi * 16 + (lane & 15);
                int c16 = kk * 2 + (lane >> 4);
                LDSM4(afr[mi], abuf + sw_off(row, c16));
            }
            unsigned bfr[4][2];
#pragma unroll
            for (int nj = 0; nj < 2; nj++) {
                int row = wn * 32 + nj * 16 + ((lane >> 4) * 8) + (lane & 7);
                int c16 = kk * 2 + ((lane >> 3) & 1);
                unsigned r4[4];
                LDSM4(r4, bbuf + sw_off(row, c16));
                bfr[nj * 2][0] = r4[0]; bfr[nj * 2][1] = r4[1];
                bfr[nj * 2 + 1][0] = r4[2]; bfr[nj * 2 + 1][1] = r4[3];
            }
#pragma unroll
            for (int mi = 0; mi < 4; mi++)
#pragma unroll
                for (int ni = 0; ni < 4; ni++)
                    mma_bf16(acc[mi][ni], afr[mi], bfr[ni]);
        }

        if (c + 2 < NCH) {
            load_chunk(c + 2);
            asm volatile("cp.async.commit_group;" ::: "memory");
        } else {
            asm volatile("cp.async.commit_group;" ::: "memory");  // empty group keeps wait counts aligned
        }
    }

    // ---- epilogue (round-8 proven) ----
    const int rq = lane >> 2;
    const int cp = lane & 3;

#pragma unroll
    for (int mi = 0; mi < 4; mi++) {
#pragma unroll
        for (int ni = 0; ni < 4; ni++) {
            int col = col0 + wn * 32 + ni * 8 + 2 * cp;
#pragma unroll
            for (int half = 0; half < 2; half++) {
                int r = row0 + wm * 64 + mi * 16 + rq + half * 8;
                if (r >= cnt) continue;
                float v0 = acc[mi][ni][half * 2];
                float v1 = acc[mi][ni][half * 2 + 1];
                if (MODE == 0) {
                    v0 = gelu_exact(v0);
                    v1 = gelu_exact(v1);
                    float h0 = __bfloat162float(__float2bfloat16(v0));
                    float h1 = __bfloat162float(__float2bfloat16(v1));
                    unsigned hp = pack_bf16(h0, h1);
                    unsigned lp = pack_bf16(v0 - h0, v1 - h1);
                    __nv_bfloat16* dst = g_act3 + ((size_t)e * CAP + r) * (size_t)(3 * FD) + col;
                    *(unsigned*)(dst)          = hp;
                    *(unsigned*)(dst + FD)     = hp;
                    *(unsigned*)(dst + 2 * FD) = lp;
                } else {
                    float* dst = g_y + ((size_t)e * CAP + r) * HD + col;
                    *(float2*)dst = make_float2(v0, v1);
                }
            }
        }
    }
}

// ---------------- combine ----------------
__global__ void combine_kernel(const float* __restrict__ residual,
                               const float* __restrict__ probs,
                               float* __restrict__ out) {
    int i = blockIdx.x * blockDim.x + threadIdx.x;
    if (i >= TT * HD / 4) return;
    int t = i / (HD / 4);
    int h4 = i % (HD / 4);
    float4 acc = ((const float4*)residual)[i];
#pragma unroll
    for (int s = 0; s < KTOP; s++) {
        int e = g_slot_e[t * KTOP + s];
        if (e < 0) continue;
        int pos = g_slot_p[t * KTOP + s];
        float g = probs[t * ED + e];
        const float4 y = *(const float4*)(g_y + ((size_t)e * CAP + pos) * HD + h4 * 4);
        acc.x += g * y.x; acc.y += g * y.y; acc.z += g * y.z; acc.w += g * y.w;
    }
    ((float4*)out)[i] = acc;
}

// ---------------- launch ----------------
extern "C" void kernel_launch(void* const* d_in, const int* in_sizes, int n_in,
                              void* d_out, int out_size) {
    const float* hidden   = (const float*)d_in[0];
    const float* residual = (const float*)d_in[1];
    const float* probs    = (const float*)d_in[2];
    const float* w1       = (const float*)d_in[4];
    const float* w2       = (const float*)d_in[5];
    float* out            = (float*)d_out;

    cudaFuncSetAttribute(gemm_mma_kernel<3 * HD, 0>,
                         cudaFuncAttributeMaxDynamicSharedMemorySize, SMEM_BYTES);
    cudaFuncSetAttribute(gemm_mma_kernel<3 * FD, 1>,
                         cudaFuncAttributeMaxDynamicSharedMemorySize, SMEM_BYTES);

    zero_cnt_kernel<<<1, 32>>>();
    router_kernel<<<TT / 256, 256>>>(probs);
    split_x_kernel<<<(TT * HD) / 256, 256>>>(hidden);
    split_w1_kernel<<<dim3(FD / 32, HD / 32, ED), dim3(32, 8)>>>(w1);
    split_w2_kernel<<<dim3(HD / 32, FD / 32, ED), dim3(32, 8)>>>(w2);

    gemm_mma_kernel<3 * HD, 0><<<dim3(FD / BN, CAP / BM, ED), NTHR, SMEM_BYTES>>>();
    gemm_mma_kernel<3 * FD, 1><<<dim3(HD / BN, CAP / BM, ED), NTHR, SMEM_BYTES>>>();

    combine_kernel<<<(TT * HD / 4 + 255) / 256, 256>>>(residual, probs, out);
}